// round 1
// baseline (speedup 1.0000x reference)
#include <cuda_runtime.h>
#include <math.h>

#define BB 32
#define TT 256
#define FF 2048
#define KK 16
#define NCC 10

// per-row scratch: rows 0..31 = abnormal side, 32..63 = normal side
__device__ float g_loss[2 * BB];
__device__ float g_vls[2 * BB];

__global__ void rows_kernel(const float* __restrict__ abn_fm,
                            const float* __restrict__ nor_fm,
                            const float* __restrict__ abn_ft,
                            const float* __restrict__ nor_ft,
                            const float* __restrict__ abn_sls,
                            const float* __restrict__ nor_sls,
                            const float* __restrict__ abn_dm,
                            const float* __restrict__ nor_dm)
{
    const int row = blockIdx.x;       // 0..63
    const int b   = row & (BB - 1);   // 0..31
    const bool is_abn = (row < BB);

    const float* fm  = is_abn ? abn_fm  : nor_fm;
    const float* dm  = is_abn ? abn_dm  : nor_dm;
    const float* sls = is_abn ? abn_sls : nor_sls;
    const float* ftb = (is_abn ? abn_ft : nor_ft);
    // feats[-1][b] : offset (NC-1)*B*T*F + b*T*F floats
    const float* ft = ftb + (size_t)(NCC - 1) * BB * TT * FF + (size_t)b * TT * FF;

    __shared__ float sdrop[TT];
    __shared__ float rval[TT];
    __shared__ int   rind[TT];
    __shared__ int   sidx[KK];

    const int tid = threadIdx.x;

    sdrop[tid] = fm[b * TT + tid] * dm[b * TT + tid];
    __syncthreads();

    // iterative top-K via argmax reduction (tie -> smaller index, like lax.top_k)
    for (int k = 0; k < KK; k++) {
        rval[tid] = sdrop[tid];
        rind[tid] = tid;
        __syncthreads();
        for (int s = TT / 2; s > 0; s >>= 1) {
            if (tid < s) {
                float v2 = rval[tid + s];
                int   i2 = rind[tid + s];
                if (v2 > rval[tid] || (v2 == rval[tid] && i2 < rind[tid])) {
                    rval[tid] = v2;
                    rind[tid] = i2;
                }
            }
            __syncthreads();
        }
        if (tid == 0) {
            sidx[k] = rind[0];
            sdrop[rind[0]] = -1.0f;   // values are >= 0, so -1 excludes it
        }
        __syncthreads();
    }

    // mean of sls over selected indices (first warp, lanes 0..15)
    if (tid < 32) {
        float v = (tid < KK) ? sls[b * TT + sidx[tid]] : 0.0f;
        #pragma unroll
        for (int off = 16; off > 0; off >>= 1)
            v += __shfl_down_sync(0xFFFFFFFFu, v, off);
        if (tid == 0) g_vls[row] = v * (1.0f / KK);
    }

    // feature gather: sum over K selected rows, accumulate sum^2 over F
    const float4* ft4 = (const float4*)ft;
    float local = 0.0f;
    #pragma unroll
    for (int i = 0; i < (FF / 4) / TT; i++) {       // 512 float4 / 256 threads = 2
        const int f4 = tid + i * TT;
        float4 acc = make_float4(0.f, 0.f, 0.f, 0.f);
        #pragma unroll
        for (int k = 0; k < KK; k++) {
            float4 v = ft4[(size_t)sidx[k] * (FF / 4) + f4];
            acc.x += v.x; acc.y += v.y; acc.z += v.z; acc.w += v.w;
        }
        local += acc.x * acc.x + acc.y * acc.y + acc.z * acc.z + acc.w * acc.w;
    }

    // block reduce local -> total sum of squares of K-sums
    rval[tid] = local;
    __syncthreads();
    for (int s = TT / 2; s > 31; s >>= 1) {
        if (tid < s) rval[tid] += rval[tid + s];
        __syncthreads();
    }
    if (tid < 32) {
        float v = rval[tid];
        #pragma unroll
        for (int off = 16; off > 0; off >>= 1)
            v += __shfl_down_sync(0xFFFFFFFFu, v, off);
        if (tid == 0) {
            // ||mean over K|| = sqrt(sum of K-sums^2) / K
            float nrm = sqrtf(v) * (1.0f / KK);
            g_loss[row] = is_abn ? fabsf(100.0f - nrm) : nrm;
        }
    }
}

__global__ void finalize_kernel(const float* __restrict__ label,
                                float* __restrict__ out)
{
    const int tid = threadIdx.x;   // 0..63
    __shared__ float s_rt[64];
    __shared__ float s_bce[64];

    float rt = 0.0f;
    if (tid < BB) {
        float l = g_loss[tid] + g_loss[BB + tid];   // loss_abn[b] + loss_norm[b]
        rt = l * l;
    }

    // vls = concat([vls_norm, vls_abn]) ; norm side stored at rows 32..63
    float v = (tid < BB) ? g_vls[BB + tid] : g_vls[tid - BB];
    float lab = label[tid];
    float logp   = fmaxf(logf(v),      -100.0f);
    float log1mp = fmaxf(log1pf(-v),   -100.0f);
    float bce = lab * logp + (1.0f - lab) * log1mp;

    s_rt[tid]  = rt;
    s_bce[tid] = bce;
    __syncthreads();
    for (int s = 32; s > 0; s >>= 1) {
        if (tid < s) { s_rt[tid] += s_rt[tid + s]; s_bce[tid] += s_bce[tid + s]; }
        __syncthreads();
    }
    if (tid == 0) {
        // mean over 2B of (la+ln)^2 == mean over B (duplication), times ALPHA
        out[0] = 1e-4f * (s_rt[0] * (1.0f / BB));
        out[1] = -s_bce[0] * (1.0f / 64.0f);
    }
}

extern "C" void kernel_launch(void* const* d_in, const int* in_sizes, int n_in,
                              void* d_out, int out_size)
{
    const float* abnr_fmagn = (const float*)d_in[0];
    const float* norm_fmagn = (const float*)d_in[1];
    const float* abnr_feats = (const float*)d_in[2];
    const float* norm_feats = (const float*)d_in[3];
    const float* abnr_sls   = (const float*)d_in[4];
    const float* norm_sls   = (const float*)d_in[5];
    const float* label      = (const float*)d_in[6];
    const float* drop_abn   = (const float*)d_in[7];
    const float* drop_norm  = (const float*)d_in[8];

    rows_kernel<<<2 * BB, TT>>>(abnr_fmagn, norm_fmagn,
                                abnr_feats, norm_feats,
                                abnr_sls, norm_sls,
                                drop_abn, drop_norm);
    finalize_kernel<<<1, 64>>>(label, (float*)d_out);
}

// round 2
// speedup vs baseline: 2.1774x; 2.1774x over previous
#include <cuda_runtime.h>
#include <math.h>

#define BB 32
#define TT 256
#define FF 2048
#define KK 16
#define NCC 10

__device__ float g_loss[2 * BB];
__device__ float g_vls[2 * BB];
__device__ unsigned int g_count = 0;

__global__ void __launch_bounds__(TT, 1) fused_kernel(
    const float* __restrict__ abn_fm,
    const float* __restrict__ nor_fm,
    const float* __restrict__ abn_ft,
    const float* __restrict__ nor_ft,
    const float* __restrict__ abn_sls,
    const float* __restrict__ nor_sls,
    const float* __restrict__ abn_dm,
    const float* __restrict__ nor_dm,
    const float* __restrict__ label,
    float* __restrict__ out)
{
    const int row = blockIdx.x;       // 0..63
    const int b   = row & (BB - 1);   // 0..31
    const bool is_abn = (row < BB);

    const float* fm  = is_abn ? abn_fm  : nor_fm;
    const float* dm  = is_abn ? abn_dm  : nor_dm;
    const float* sls = is_abn ? abn_sls : nor_sls;
    const float* ftb = (is_abn ? abn_ft : nor_ft);
    // feats[-1][b]
    const float* ft = ftb + (size_t)(NCC - 1) * BB * TT * FF + (size_t)b * TT * FF;

    const int tid  = threadIdx.x;
    const int wid  = tid >> 5;
    const int lane = tid & 31;

    // ---- load drop values into registers: lane l, slot j -> t = j*32 + l ----
    // key = (float_bits << 32) | ~idx  : monotone in value (>=0), tie -> smaller idx
    unsigned long long kk[8];
    #pragma unroll
    for (int j = 0; j < 8; j++) {
        int t = j * 32 + lane;
        float v = fm[b * TT + t] * dm[b * TT + t];
        kk[j] = ((unsigned long long)__float_as_uint(v) << 32)
              | (unsigned int)(~(unsigned int)t);
    }

    // ---- redundant per-warp top-16 (no barriers) ----
    int idxs[KK];
    float slssum = 0.0f;
    #pragma unroll
    for (int k = 0; k < KK; k++) {
        unsigned long long best = kk[0];
        #pragma unroll
        for (int j = 1; j < 8; j++) best = (kk[j] > best) ? kk[j] : best;
        #pragma unroll
        for (int off = 16; off > 0; off >>= 1) {
            unsigned long long o = __shfl_xor_sync(0xFFFFFFFFu, best, off);
            best = (o > best) ? o : best;
        }
        unsigned int widx = ~(unsigned int)(best & 0xFFFFFFFFull);
        idxs[k] = (int)widx;
        #pragma unroll
        for (int j = 0; j < 8; j++) if (kk[j] == best) kk[j] = 0ull;
        if (tid == 0) slssum += sls[b * TT + (int)widx];
    }

    // ---- feature gather: warp w owns f4 range [w*64, w*64+64) ----
    const float4* ft4 = (const float4*)ft;
    float local = 0.0f;
    #pragma unroll
    for (int i = 0; i < 2; i++) {
        const int f4 = wid * 64 + i * 32 + lane;
        float4 acc = make_float4(0.f, 0.f, 0.f, 0.f);
        #pragma unroll
        for (int k = 0; k < KK; k++) {
            float4 v = ft4[(size_t)idxs[k] * (FF / 4) + f4];
            acc.x += v.x; acc.y += v.y; acc.z += v.z; acc.w += v.w;
        }
        local += acc.x * acc.x + acc.y * acc.y + acc.z * acc.z + acc.w * acc.w;
    }

    // ---- block reduce sum of squares ----
    __shared__ float swarp[8];
    __shared__ unsigned int s_last;
    #pragma unroll
    for (int off = 16; off > 0; off >>= 1)
        local += __shfl_xor_sync(0xFFFFFFFFu, local, off);
    if (lane == 0) swarp[wid] = local;
    __syncthreads();

    if (tid == 0) {
        float tot = 0.0f;
        #pragma unroll
        for (int w = 0; w < 8; w++) tot += swarp[w];
        float nrm = sqrtf(tot) * (1.0f / KK);
        g_loss[row] = is_abn ? fabsf(100.0f - nrm) : nrm;
        g_vls[row]  = slssum * (1.0f / KK);
        __threadfence();
        s_last = (atomicAdd(&g_count, 1u) == 2u * BB - 1u) ? 1u : 0u;
    }
    __syncthreads();

    // ---- last block performs finalize ----
    if (s_last) {
        __shared__ float s_rt[64];
        __shared__ float s_bce[64];
        volatile float* vloss = g_loss;
        volatile float* vvls  = g_vls;

        float rt = 0.0f, bce = 0.0f;
        if (tid < 64) {
            if (tid < BB) {
                float l = vloss[tid] + vloss[BB + tid];
                rt = l * l;
            }
            // vls = concat([vls_norm, vls_abn]); norm rows are 32..63
            float v = (tid < BB) ? vvls[BB + tid] : vvls[tid - BB];
            float lab = label[tid];
            float logp   = fmaxf(logf(v),    -100.0f);
            float log1mp = fmaxf(log1pf(-v), -100.0f);
            bce = lab * logp + (1.0f - lab) * log1mp;
            s_rt[tid]  = rt;
            s_bce[tid] = bce;
        }
        __syncthreads();
        for (int s = 32; s > 0; s >>= 1) {
            if (tid < s) { s_rt[tid] += s_rt[tid + s]; s_bce[tid] += s_bce[tid + s]; }
            __syncthreads();
        }
        if (tid == 0) {
            out[0] = 1e-4f * (s_rt[0] * (1.0f / BB));
            out[1] = -s_bce[0] * (1.0f / 64.0f);
            g_count = 0;   // reset for next graph replay
        }
    }
}

extern "C" void kernel_launch(void* const* d_in, const int* in_sizes, int n_in,
                              void* d_out, int out_size)
{
    const float* abnr_fmagn = (const float*)d_in[0];
    const float* norm_fmagn = (const float*)d_in[1];
    const float* abnr_feats = (const float*)d_in[2];
    const float* norm_feats = (const float*)d_in[3];
    const float* abnr_sls   = (const float*)d_in[4];
    const float* norm_sls   = (const float*)d_in[5];
    const float* label      = (const float*)d_in[6];
    const float* drop_abn   = (const float*)d_in[7];
    const float* drop_norm  = (const float*)d_in[8];

    fused_kernel<<<2 * BB, TT>>>(abnr_fmagn, norm_fmagn,
                                 abnr_feats, norm_feats,
                                 abnr_sls, norm_sls,
                                 drop_abn, drop_norm,
                                 label, (float*)d_out);
}